// round 11
// baseline (speedup 1.0000x reference)
#include <cuda_runtime.h>
#include <cuda_fp16.h>
#include <cstdint>

// ---------------- problem constants ----------------
namespace {
constexpr int NROWS = 65536;
constexpr int BSAMP = 4096;
constexpr int INSZ  = 64;
constexpr int HID   = 512;
constexpr int DDIM  = 256;
constexpr int EMBK  = INSZ + HID + DDIM;  // 832
constexpr int G3    = 3 * HID;            // 1536

constexpr int BM = 128, BN = 128, BK = 32, NTHR = 256;
constexpr int LDSH = 40;                         // padded smem row stride (halves) = 80B
constexpr int TILE_BYTES  = BM * LDSH * 2;       // 10240 per operand tile
constexpr int STAGE_BYTES = 2 * TILE_BYTES;      // 20480
constexpr int NSTAGE = 3;
constexpr int SMEM_BYTES = NSTAGE * STAGE_BYTES + 512;   // + sids
constexpr int GRID_Y1 = G3 / BN;                 // 12 (split point of merged gi|gh launch)
}

// ---------------- scratch (__device__ globals) ----------------
__device__ __half g_gi  [(size_t)NROWS * G3];
__device__ __half g_gh  [(size_t)NROWS * G3];
__device__ __half g_emb [(size_t)NROWS * HID];
__device__ __half g_wt  [(size_t)HID * EMBK];    // W_emb^T in half
__device__ __half g_wih [(size_t)G3 * HID];
__device__ __half g_whh [(size_t)G3 * HID];
__device__ __half g_nt  [(size_t)NROWS * INSZ];
__device__ __half g_ds  [(size_t)NROWS * DDIM];
__device__ __half g_tj  [(size_t)BSAMP * HID];
__device__ __half g_htt [(size_t)NROWS * HID];

// ---------------- helpers ----------------
__device__ __forceinline__ uint32_t smem_u32(const void* p) {
    uint32_t a;
    asm("{ .reg .u64 t; cvta.to.shared.u64 t, %1; cvt.u32.u64 %0, t; }" : "=r"(a) : "l"(p));
    return a;
}
#define CP_ASYNC16(dst, src) \
    asm volatile("cp.async.cg.shared.global [%0], [%1], 16;\n" :: "r"(dst), "l"(src))

// fp16-accumulator MMA: d (f16x2 x2) = a*b + d
__device__ __forceinline__ void mma_f16h(uint32_t* d, const uint32_t* a, const uint32_t* b) {
    asm volatile(
        "mma.sync.aligned.m16n8k16.row.col.f16.f16.f16.f16 "
        "{%0,%1}, {%2,%3,%4,%5}, {%6,%7}, {%0,%1};"
        : "+r"(d[0]), "+r"(d[1])
        : "r"(a[0]), "r"(a[1]), "r"(a[2]), "r"(a[3]), "r"(b[0]), "r"(b[1]));
}
#define LDSM_X4(r, addr) \
    asm volatile("ldmatrix.sync.aligned.m8n8.x4.shared.b16 {%0,%1,%2,%3}, [%4];" \
                 : "=r"((r)[0]), "=r"((r)[1]), "=r"((r)[2]), "=r"((r)[3]) : "r"(addr))
#define LDSM_X2(r, addr) \
    asm volatile("ldmatrix.sync.aligned.m8n8.x2.shared.b16 {%0,%1}, [%2];" \
                 : "=r"((r)[0]), "=r"((r)[1]) : "r"(addr))

__device__ __forceinline__ float sigf(float x) { return 1.f / (1.f + expf(-x)); }

// ---------------- merged fp32 -> fp16 conversion ----------------
struct CvtSegs {
    const float* src[6];
    __half*      dst[6];
    int          end8[6];
};

__global__ void __launch_bounds__(256) cvt_all_k(CvtSegs segs) {
    int i = blockIdx.x * 256 + threadIdx.x;
    if (i >= segs.end8[5]) return;
    int s = 0;
    #pragma unroll
    for (int j = 0; j < 5; j++) s += (i >= segs.end8[j]);
    int base = (s == 0) ? 0 : segs.end8[s - 1];
    int li = i - base;
    const float4* in = (const float4*)segs.src[s];
    float4 v0 = in[li * 2];
    float4 v1 = in[li * 2 + 1];
    __half2 h[4];
    h[0] = __floats2half2_rn(v0.x, v0.y);
    h[1] = __floats2half2_rn(v0.z, v0.w);
    h[2] = __floats2half2_rn(v1.x, v1.y);
    h[3] = __floats2half2_rn(v1.z, v1.w);
    ((uint4*)segs.dst[s])[li] = *(uint4*)h;
}

__global__ void transpose_cvt_k(const float* __restrict__ W, __half* __restrict__ Wt) {
    __shared__ float t[32][33];
    int bx = blockIdx.x * 32;   // k
    int by = blockIdx.y * 32;   // n
    int tx = threadIdx.x, ty = threadIdx.y;
    #pragma unroll
    for (int i = 0; i < 4; i++)
        t[ty + i * 8][tx] = W[(size_t)(bx + ty + i * 8) * HID + (by + tx)];
    __syncthreads();
    #pragma unroll
    for (int i = 0; i < 4; i++)
        Wt[(size_t)(by + ty + i * 8) * EMBK + (bx + tx)] = __float2half(t[tx][ty + i * 8]);
}

// ---------------- fp16 mma.sync GEMM, f16-acc chunks (K=64) + f32 spill -----
// C[m, n0:n0+BN] = act( A[m,:K] @ B[n,:K]^T + bias ), C stored as __half.
// AMODE 0: A gathered (neigh | traj[sid] | dist)
// AMODE 1: dual GEMM — blockIdx.y < GRID_Y1 uses (A,B,bias,C), else (A2,B2,bias2,C2)
template<int AMODE, bool RELU>
__global__ void __launch_bounds__(NTHR)
gemm_tc(const __half* __restrict__ A,
        const __half* __restrict__ neigh,
        const __half* __restrict__ traj,
        const __half* __restrict__ dist,
        const int*   __restrict__ starts,
        const __half* __restrict__ B,
        const float* __restrict__ bias,
        __half* __restrict__ C,
        int K, int ldb, int ldc,
        const __half* A2, const __half* B2, const float* bias2, __half* C2)
{
    extern __shared__ __align__(16) char smem[];
    int* sids = (int*)(smem + NSTAGE * STAGE_BYTES);

    const int tid  = threadIdx.x;
    const int lane = tid & 31;
    const int warp = tid >> 5;
    const int wm = warp >> 2;
    const int wn = warp & 3;
    const int m0 = blockIdx.x * BM;

    int ny = blockIdx.y;
    if (AMODE == 1 && ny >= GRID_Y1) {
        ny -= GRID_Y1;
        A = A2; B = B2; bias = bias2; C = C2;
    }
    const int n0 = ny * BN;

    if (AMODE == 0 && tid < BM) {
        int row = m0 + tid;
        int lo = 0, hi = BSAMP;
        while (lo < hi) {
            int mid = (lo + hi) >> 1;
            if (starts[mid] <= row) lo = mid + 1; else hi = mid;
        }
        sids[tid] = lo - 1;
    }
    if (AMODE == 0) __syncthreads();

    const uint32_t sbase = smem_u32(smem);

    auto load_stage = [&](int s) {
        const uint32_t st = sbase + (uint32_t)((s % NSTAGE) * STAGE_BYTES);
        const int k0 = s * BK;
        #pragma unroll
        for (int i = 0; i < 2; i++) {
            int q = tid + i * NTHR;
            int row = q >> 2, c8 = (q & 3) * 8;
            uint32_t dst = st + (uint32_t)(row * LDSH + c8) * 2u;
            const __half* src;
            int gm = m0 + row;
            int kh = k0 + c8;
            if (AMODE == 1) {
                src = A + (size_t)gm * K + kh;
            } else {
                if (kh < INSZ)
                    src = neigh + (size_t)gm * INSZ + kh;
                else if (kh < INSZ + HID)
                    src = traj + (size_t)sids[row] * HID + (kh - INSZ);
                else
                    src = dist + (size_t)gm * DDIM + (kh - INSZ - HID);
            }
            CP_ASYNC16(dst, src);
        }
        const uint32_t bb = st + (uint32_t)TILE_BYTES;
        #pragma unroll
        for (int i = 0; i < 2; i++) {
            int q = tid + i * NTHR;
            int row = q >> 2, c8 = (q & 3) * 8;
            uint32_t dst = bb + (uint32_t)(row * LDSH + c8) * 2u;
            const __half* src = B + (size_t)(n0 + row) * ldb + (k0 + c8);
            CP_ASYNC16(dst, src);
        }
    };

    float acc[4][4][4];
    #pragma unroll
    for (int mt = 0; mt < 4; mt++)
        #pragma unroll
        for (int nt = 0; nt < 4; nt++)
            #pragma unroll
            for (int j = 0; j < 4; j++) acc[mt][nt][j] = 0.f;

    uint32_t h_acc[4][4][2];   // f16x2 chunk accumulators (K=64 chunks)

    const uint32_t a_lane = (uint32_t)((wm * 64 + (lane & 15)) * LDSH + (lane >> 4) * 8) * 2u;
    const uint32_t b_lane = (uint32_t)(TILE_BYTES) +
        (uint32_t)((wn * 32 + (lane & 7)) * LDSH + ((lane >> 3) & 1) * 8) * 2u;

    const int NS = K / BK;     // 16 (K=512) or 26 (K=832) — both even
    load_stage(0);
    asm volatile("cp.async.commit_group;\n" ::: "memory");
    load_stage(1);
    asm volatile("cp.async.commit_group;\n" ::: "memory");

    for (int s = 0; s < NS; ++s) {
        if (s + 2 < NS) load_stage(s + 2);
        asm volatile("cp.async.commit_group;\n" ::: "memory");
        asm volatile("cp.async.wait_group 2;\n" ::: "memory");
        __syncthreads();

        if ((s & 1) == 0) {                  // chunk start: zero f16 accumulators
            #pragma unroll
            for (int mt = 0; mt < 4; mt++)
                #pragma unroll
                for (int nt = 0; nt < 4; nt++) {
                    h_acc[mt][nt][0] = 0u;
                    h_acc[mt][nt][1] = 0u;
                }
        }

        const uint32_t st = sbase + (uint32_t)((s % NSTAGE) * STAGE_BYTES);
        #pragma unroll
        for (int kk = 0; kk < 2; kk++) {
            uint32_t a[4][4], b[4][2];
            #pragma unroll
            for (int mt = 0; mt < 4; mt++)
                LDSM_X4(a[mt], st + a_lane + (uint32_t)(mt * 16 * LDSH * 2 + kk * 32));
            #pragma unroll
            for (int nt = 0; nt < 4; nt++)
                LDSM_X2(b[nt], st + b_lane + (uint32_t)(nt * 8 * LDSH * 2 + kk * 32));
            #pragma unroll
            for (int mt = 0; mt < 4; mt++)
                #pragma unroll
                for (int nt = 0; nt < 4; nt++)
                    mma_f16h(h_acc[mt][nt], a[mt], b[nt]);
        }

        if (s & 1) {                         // chunk end: spill f16 -> f32
            #pragma unroll
            for (int mt = 0; mt < 4; mt++)
                #pragma unroll
                for (int nt = 0; nt < 4; nt++) {
                    float2 lo = __half22float2(*(__half2*)&h_acc[mt][nt][0]);
                    float2 hi = __half22float2(*(__half2*)&h_acc[mt][nt][1]);
                    acc[mt][nt][0] += lo.x;
                    acc[mt][nt][1] += lo.y;
                    acc[mt][nt][2] += hi.x;
                    acc[mt][nt][3] += hi.y;
                }
        }
        __syncthreads();
    }

    // ---------------- epilogue (half stores) ----------------
    #pragma unroll
    for (int mt = 0; mt < 4; mt++) {
        #pragma unroll
        for (int nt = 0; nt < 4; nt++) {
            int col = n0 + wn * 32 + nt * 8 + 2 * (lane & 3);
            float2 bv = *(const float2*)(bias + col);
            int r0 = m0 + wm * 64 + mt * 16 + (lane >> 2);
            float v0 = acc[mt][nt][0] + bv.x;
            float v1 = acc[mt][nt][1] + bv.y;
            float v2 = acc[mt][nt][2] + bv.x;
            float v3 = acc[mt][nt][3] + bv.y;
            if (RELU) {
                v0 = fmaxf(v0, 0.f); v1 = fmaxf(v1, 0.f);
                v2 = fmaxf(v2, 0.f); v3 = fmaxf(v3, 0.f);
            }
            *(__half2*)(C + (size_t)r0 * ldc + col)       = __floats2half2_rn(v0, v1);
            *(__half2*)(C + (size_t)(r0 + 8) * ldc + col) = __floats2half2_rn(v2, v3);
        }
    }
}

// ---------------- GRU gates (fp16 gi/gh inputs, fp32 ht/out) ----------------
__device__ __forceinline__ float gru1(float ir, float iz, float inn,
                                      float hr, float hz, float hn, float h)
{
    float r = sigf(ir + hr);
    float z = sigf(iz + hz);
    float nn = tanhf(fmaf(r, hn, inn));
    return fmaf(z, h - nn, nn);
}

__global__ void __launch_bounds__(256)
gates_k(const __half* __restrict__ gi, const __half* __restrict__ gh,
        const float* __restrict__ ht, float* __restrict__ out)
{
    int idx = blockIdx.x * 256 + threadIdx.x;
    int n  = idx >> 7;
    int h4 = (idx & 127) << 2;
    const __half* gir = gi + (size_t)n * G3;
    const __half* ghr = gh + (size_t)n * G3;

    __half2 irh[2], izh[2], inh[2], hrh[2], hzh[2], hnh[2];
    *(uint2*)irh = *(const uint2*)(gir + h4);
    *(uint2*)izh = *(const uint2*)(gir + HID + h4);
    *(uint2*)inh = *(const uint2*)(gir + 2 * HID + h4);
    *(uint2*)hrh = *(const uint2*)(ghr + h4);
    *(uint2*)hzh = *(const uint2*)(ghr + HID + h4);
    *(uint2*)hnh = *(const uint2*)(ghr + 2 * HID + h4);
    float4 h = *(const float4*)(ht + (size_t)n * HID + h4);

    float2 ir0 = __half22float2(irh[0]), ir1 = __half22float2(irh[1]);
    float2 iz0 = __half22float2(izh[0]), iz1 = __half22float2(izh[1]);
    float2 in0 = __half22float2(inh[0]), in1 = __half22float2(inh[1]);
    float2 hr0 = __half22float2(hrh[0]), hr1 = __half22float2(hrh[1]);
    float2 hz0 = __half22float2(hzh[0]), hz1 = __half22float2(hzh[1]);
    float2 hn0 = __half22float2(hnh[0]), hn1 = __half22float2(hnh[1]);

    float4 o;
    o.x = gru1(ir0.x, iz0.x, in0.x, hr0.x, hz0.x, hn0.x, h.x);
    o.y = gru1(ir0.y, iz0.y, in0.y, hr0.y, hz0.y, hn0.y, h.y);
    o.z = gru1(ir1.x, iz1.x, in1.x, hr1.x, hz1.x, hn1.x, h.z);
    o.w = gru1(ir1.y, iz1.y, in1.y, hr1.y, hz1.y, hn1.y, h.w);
    *(float4*)(out + (size_t)n * HID + h4) = o;
}

// ---------------- host ----------------
extern "C" void kernel_launch(void* const* d_in, const int* in_sizes, int n_in,
                              void* d_out, int out_size)
{
    const float* traj  = (const float*)d_in[0];
    const float* neigh = (const float*)d_in[1];
    const float* dist  = (const float*)d_in[2];
    const float* ht    = (const float*)d_in[3];
    const float* W_emb = (const float*)d_in[4];
    const float* b_emb = (const float*)d_in[5];
    const float* w_ih  = (const float*)d_in[6];
    const float* w_hh  = (const float*)d_in[7];
    const float* b_ih  = (const float*)d_in[8];
    const float* b_hh  = (const float*)d_in[9];
    const int*   starts= (const int*)  d_in[10];
    float* out = (float*)d_out;

    __half *gi_p, *gh_p, *emb_p, *wt_p, *wih_p, *whh_p, *nt_p, *ds_p, *tj_p, *htt_p;
    cudaGetSymbolAddress((void**)&gi_p,  g_gi);
    cudaGetSymbolAddress((void**)&gh_p,  g_gh);
    cudaGetSymbolAddress((void**)&emb_p, g_emb);
    cudaGetSymbolAddress((void**)&wt_p,  g_wt);
    cudaGetSymbolAddress((void**)&wih_p, g_wih);
    cudaGetSymbolAddress((void**)&whh_p, g_whh);
    cudaGetSymbolAddress((void**)&nt_p,  g_nt);
    cudaGetSymbolAddress((void**)&ds_p,  g_ds);
    cudaGetSymbolAddress((void**)&tj_p,  g_tj);
    cudaGetSymbolAddress((void**)&htt_p, g_htt);

    cudaFuncSetAttribute(gemm_tc<0, true>,
                         cudaFuncAttributeMaxDynamicSharedMemorySize, SMEM_BYTES);
    cudaFuncSetAttribute(gemm_tc<1, false>,
                         cudaFuncAttributeMaxDynamicSharedMemorySize, SMEM_BYTES);

    CvtSegs segs;
    const float* srcs[6] = {neigh, dist, traj, ht, w_ih, w_hh};
    __half* dsts[6]      = {nt_p, ds_p, tj_p, htt_p, wih_p, whh_p};
    int sizes8[6] = {
        NROWS * INSZ / 8, NROWS * DDIM / 8, BSAMP * HID / 8,
        NROWS * HID / 8, G3 * HID / 8, G3 * HID / 8
    };
    int acc8 = 0;
    for (int i = 0; i < 6; i++) {
        segs.src[i] = srcs[i];
        segs.dst[i] = dsts[i];
        acc8 += sizes8[i];
        segs.end8[i] = acc8;
    }
    cvt_all_k<<<(acc8 + 255) / 256, 256>>>(segs);
    transpose_cvt_k<<<dim3(EMBK / 32, HID / 32), dim3(32, 8)>>>(W_emb, wt_p);

    // emb = relu(X @ W_emb + b), X gathered; output half
    gemm_tc<0, true><<<dim3(NROWS / BM, HID / BN), NTHR, SMEM_BYTES>>>(
        nullptr, nt_p, tj_p, ds_p, starts, wt_p, b_emb, emb_p, EMBK, EMBK, HID,
        nullptr, nullptr, nullptr, nullptr);

    // merged: gi = emb @ w_ih^T + b_ih  |  gh = ht @ w_hh^T + b_hh
    gemm_tc<1, false><<<dim3(NROWS / BM, 2 * GRID_Y1), NTHR, SMEM_BYTES>>>(
        emb_p, nullptr, nullptr, nullptr, nullptr, wih_p, b_ih, gi_p, HID, HID, G3,
        htt_p, whh_p, b_hh, gh_p);

    gates_k<<<(NROWS * HID / 4) / 256, 256>>>(gi_p, gh_p, ht, out);
}

// round 13
// speedup vs baseline: 1.5063x; 1.5063x over previous
#include <cuda_runtime.h>
#include <cuda_fp16.h>
#include <cstdint>

// ---------------- problem constants ----------------
namespace {
constexpr int NROWS = 65536;
constexpr int BSAMP = 4096;
constexpr int INSZ  = 64;
constexpr int HID   = 512;
constexpr int DDIM  = 256;
constexpr int EMBK  = INSZ + HID + DDIM;  // 832
constexpr int KEMB  = INSZ + DDIM;        // 320 (emb GEMM after traj split)
constexpr int G3    = 3 * HID;            // 1536

constexpr int BM = 128, BN = 128, BK = 32, NTHR = 256;
constexpr int LDSH = 40;                         // padded smem row stride (halves) = 80B
constexpr int TILE_BYTES  = BM * LDSH * 2;       // 10240 per operand tile
constexpr int STAGE_BYTES = 2 * TILE_BYTES;      // 20480
constexpr int NSTAGE = 3;
constexpr int SMEM_BYTES = NSTAGE * STAGE_BYTES + 512;   // + sids
constexpr int GRID_Y1 = G3 / BN;                 // 12 (split of merged gi|gh launch)
}

// ---------------- scratch (__device__ globals) ----------------
__device__ __half g_gi  [(size_t)NROWS * G3];
__device__ __half g_gh  [(size_t)NROWS * G3];
__device__ __half g_emb [(size_t)NROWS * HID];
__device__ __half g_temb[(size_t)BSAMP * HID];   // T = traj @ W2  [4096, 512]
__device__ __half g_wt  [(size_t)HID * EMBK];    // W_emb^T in half [n][k]
__device__ __half g_wih [(size_t)G3 * HID];
__device__ __half g_whh [(size_t)G3 * HID];
__device__ __half g_nt  [(size_t)NROWS * INSZ];
__device__ __half g_ds  [(size_t)NROWS * DDIM];
__device__ __half g_tj  [(size_t)BSAMP * HID];
__device__ __half g_htt [(size_t)NROWS * HID];
__device__ float  g_zeros[HID];                  // zero bias (static zero-init)

// ---------------- helpers ----------------
__device__ __forceinline__ uint32_t smem_u32(const void* p) {
    uint32_t a;
    asm("{ .reg .u64 t; cvta.to.shared.u64 t, %1; cvt.u32.u64 %0, t; }" : "=r"(a) : "l"(p));
    return a;
}
#define CP_ASYNC16(dst, src) \
    asm volatile("cp.async.cg.shared.global [%0], [%1], 16;\n" :: "r"(dst), "l"(src))

__device__ __forceinline__ void mma_f16(float* c, const uint32_t* a, const uint32_t* b) {
    asm volatile(
        "mma.sync.aligned.m16n8k16.row.col.f32.f16.f16.f32 "
        "{%0,%1,%2,%3}, {%4,%5,%6,%7}, {%8,%9}, {%0,%1,%2,%3};"
        : "+f"(c[0]), "+f"(c[1]), "+f"(c[2]), "+f"(c[3])
        : "r"(a[0]), "r"(a[1]), "r"(a[2]), "r"(a[3]), "r"(b[0]), "r"(b[1]));
}
#define LDSM_X4(r, addr) \
    asm volatile("ldmatrix.sync.aligned.m8n8.x4.shared.b16 {%0,%1,%2,%3}, [%4];" \
                 : "=r"((r)[0]), "=r"((r)[1]), "=r"((r)[2]), "=r"((r)[3]) : "r"(addr))
#define LDSM_X2(r, addr) \
    asm volatile("ldmatrix.sync.aligned.m8n8.x2.shared.b16 {%0,%1}, [%2];" \
                 : "=r"((r)[0]), "=r"((r)[1]) : "r"(addr))

__device__ __forceinline__ float sigf(float x) { return 1.f / (1.f + expf(-x)); }

// ---------------- merged fp32 -> fp16 conversion ----------------
struct CvtSegs {
    const float* src[6];
    __half*      dst[6];
    int          end8[6];
};

__global__ void __launch_bounds__(256) cvt_all_k(CvtSegs segs) {
    int i = blockIdx.x * 256 + threadIdx.x;
    if (i >= segs.end8[5]) return;
    int s = 0;
    #pragma unroll
    for (int j = 0; j < 5; j++) s += (i >= segs.end8[j]);
    int base = (s == 0) ? 0 : segs.end8[s - 1];
    int li = i - base;
    const float4* in = (const float4*)segs.src[s];
    float4 v0 = in[li * 2];
    float4 v1 = in[li * 2 + 1];
    __half2 h[4];
    h[0] = __floats2half2_rn(v0.x, v0.y);
    h[1] = __floats2half2_rn(v0.z, v0.w);
    h[2] = __floats2half2_rn(v1.x, v1.y);
    h[3] = __floats2half2_rn(v1.z, v1.w);
    ((uint4*)segs.dst[s])[li] = *(uint4*)h;
}

__global__ void transpose_cvt_k(const float* __restrict__ W, __half* __restrict__ Wt) {
    __shared__ float t[32][33];
    int bx = blockIdx.x * 32;   // k
    int by = blockIdx.y * 32;   // n
    int tx = threadIdx.x, ty = threadIdx.y;
    #pragma unroll
    for (int i = 0; i < 4; i++)
        t[ty + i * 8][tx] = W[(size_t)(bx + ty + i * 8) * HID + (by + tx)];
    __syncthreads();
    #pragma unroll
    for (int i = 0; i < 4; i++)
        Wt[(size_t)(by + ty + i * 8) * EMBK + (bx + tx)] = __float2half(t[tx][ty + i * 8]);
}

// ---------------- fp16 mma.sync GEMM (R7 config) ----------------
// AMODE 0: emb GEMM — A = [neigh | dist] (K=320), epilogue adds gathered
//          T[sid[row]] before bias+ReLU.
// AMODE 1: plain row-major A; dual launch: blockIdx.y >= GRID_Y1 switches to
//          the second operand set (A2,B2,bias2,C2).
// B k-index remap for AMODE 0: kh<64 -> wt col kh ; else wt col kh+512.
template<int AMODE, bool RELU>
__global__ void __launch_bounds__(NTHR, 2)
gemm_tc(const __half* __restrict__ A,
        const __half* __restrict__ neigh,
        const __half* __restrict__ dist,
        const int*   __restrict__ starts,
        const __half* __restrict__ B,
        const float* __restrict__ bias,
        __half* __restrict__ C,
        int K, int ldb, int ldc,
        const __half* __restrict__ Temb,
        const __half* A2, const __half* B2, const float* bias2, __half* C2)
{
    extern __shared__ __align__(16) char smem[];
    int* sids = (int*)(smem + NSTAGE * STAGE_BYTES);

    const int tid  = threadIdx.x;
    const int lane = tid & 31;
    const int warp = tid >> 5;
    const int wm = warp >> 2;
    const int wn = warp & 3;
    const int m0 = blockIdx.x * BM;

    int ny = blockIdx.y;
    if (AMODE == 1 && ny >= GRID_Y1) {
        ny -= GRID_Y1;
        A = A2; B = B2; bias = bias2; C = C2;
    }
    const int n0 = ny * BN;

    if (AMODE == 0 && tid < BM) {
        int row = m0 + tid;
        int lo = 0, hi = BSAMP;
        while (lo < hi) {
            int mid = (lo + hi) >> 1;
            if (starts[mid] <= row) lo = mid + 1; else hi = mid;
        }
        sids[tid] = lo - 1;
    }
    if (AMODE == 0) __syncthreads();

    const uint32_t sbase = smem_u32(smem);

    auto load_stage = [&](int s) {
        const uint32_t st = sbase + (uint32_t)((s % NSTAGE) * STAGE_BYTES);
        const int k0 = s * BK;
        #pragma unroll
        for (int i = 0; i < 2; i++) {
            int q = tid + i * NTHR;
            int row = q >> 2, c8 = (q & 3) * 8;
            uint32_t dst = st + (uint32_t)(row * LDSH + c8) * 2u;
            const __half* src;
            int gm = m0 + row;
            int kh = k0 + c8;
            if (AMODE == 1) {
                src = A + (size_t)gm * K + kh;
            } else {
                src = (kh < INSZ) ? neigh + (size_t)gm * INSZ + kh
                                  : dist + (size_t)gm * DDIM + (kh - INSZ);
            }
            CP_ASYNC16(dst, src);
        }
        const uint32_t bb = st + (uint32_t)TILE_BYTES;
        #pragma unroll
        for (int i = 0; i < 2; i++) {
            int q = tid + i * NTHR;
            int row = q >> 2, c8 = (q & 3) * 8;
            uint32_t dst = bb + (uint32_t)(row * LDSH + c8) * 2u;
            int kh = k0 + c8;
            int kb = (AMODE == 0 && kh >= INSZ) ? kh + HID : kh;   // skip traj cols
            const __half* src = B + (size_t)(n0 + row) * ldb + kb;
            CP_ASYNC16(dst, src);
        }
    };

    float acc[4][4][4];
    #pragma unroll
    for (int mt = 0; mt < 4; mt++)
        #pragma unroll
        for (int nt = 0; nt < 4; nt++)
            #pragma unroll
            for (int j = 0; j < 4; j++) acc[mt][nt][j] = 0.f;

    const uint32_t a_lane = (uint32_t)((wm * 64 + (lane & 15)) * LDSH + (lane >> 4) * 8) * 2u;
    const uint32_t b_lane = (uint32_t)(TILE_BYTES) +
        (uint32_t)((wn * 32 + (lane & 7)) * LDSH + ((lane >> 3) & 1) * 8) * 2u;

    const int NS = K / BK;
    load_stage(0);
    asm volatile("cp.async.commit_group;\n" ::: "memory");
    load_stage(1);
    asm volatile("cp.async.commit_group;\n" ::: "memory");

    for (int s = 0; s < NS; ++s) {
        if (s + 2 < NS) load_stage(s + 2);
        asm volatile("cp.async.commit_group;\n" ::: "memory");
        asm volatile("cp.async.wait_group 2;\n" ::: "memory");
        __syncthreads();

        const uint32_t st = sbase + (uint32_t)((s % NSTAGE) * STAGE_BYTES);
        #pragma unroll
        for (int kk = 0; kk < 2; kk++) {
            uint32_t a[4][4], b[4][2];
            #pragma unroll
            for (int mt = 0; mt < 4; mt++)
                LDSM_X4(a[mt], st + a_lane + (uint32_t)(mt * 16 * LDSH * 2 + kk * 32));
            #pragma unroll
            for (int nt = 0; nt < 4; nt++)
                LDSM_X2(b[nt], st + b_lane + (uint32_t)(nt * 8 * LDSH * 2 + kk * 32));
            #pragma unroll
            for (int mt = 0; mt < 4; mt++)
                #pragma unroll
                for (int nt = 0; nt < 4; nt++)
                    mma_f16(acc[mt][nt], a[mt], b[nt]);
        }
        __syncthreads();
    }

    // ---------------- epilogue (half stores; AMODE 0 gathers T[sid]) --------
    #pragma unroll
    for (int mt = 0; mt < 4; mt++) {
        #pragma unroll
        for (int nt = 0; nt < 4; nt++) {
            int col = n0 + wn * 32 + nt * 8 + 2 * (lane & 3);
            float2 bv = *(const float2*)(bias + col);
            int lr0 = wm * 64 + mt * 16 + (lane >> 2);
            int r0 = m0 + lr0;
            float v0 = acc[mt][nt][0] + bv.x;
            float v1 = acc[mt][nt][1] + bv.y;
            float v2 = acc[mt][nt][2] + bv.x;
            float v3 = acc[mt][nt][3] + bv.y;
            if (AMODE == 0) {
                float2 tA = __half22float2(
                    *(const __half2*)(Temb + (size_t)sids[lr0] * HID + col));
                float2 tB = __half22float2(
                    *(const __half2*)(Temb + (size_t)sids[lr0 + 8] * HID + col));
                v0 += tA.x; v1 += tA.y; v2 += tB.x; v3 += tB.y;
            }
            if (RELU) {
                v0 = fmaxf(v0, 0.f); v1 = fmaxf(v1, 0.f);
                v2 = fmaxf(v2, 0.f); v3 = fmaxf(v3, 0.f);
            }
            *(__half2*)(C + (size_t)r0 * ldc + col)       = __floats2half2_rn(v0, v1);
            *(__half2*)(C + (size_t)(r0 + 8) * ldc + col) = __floats2half2_rn(v2, v3);
        }
    }
}

// ---------------- GRU gates (fp16 gi/gh inputs, fp32 ht/out) ----------------
__device__ __forceinline__ float gru1(float ir, float iz, float inn,
                                      float hr, float hz, float hn, float h)
{
    float r = sigf(ir + hr);
    float z = sigf(iz + hz);
    float nn = tanhf(fmaf(r, hn, inn));
    return fmaf(z, h - nn, nn);
}

__global__ void __launch_bounds__(256)
gates_k(const __half* __restrict__ gi, const __half* __restrict__ gh,
        const float* __restrict__ ht, float* __restrict__ out)
{
    int idx = blockIdx.x * 256 + threadIdx.x;
    int n  = idx >> 7;
    int h4 = (idx & 127) << 2;
    const __half* gir = gi + (size_t)n * G3;
    const __half* ghr = gh + (size_t)n * G3;

    __half2 irh[2], izh[2], inh[2], hrh[2], hzh[2], hnh[2];
    *(uint2*)irh = *(const uint2*)(gir + h4);
    *(uint2*)izh = *(const uint2*)(gir + HID + h4);
    *(uint2*)inh = *(const uint2*)(gir + 2 * HID + h4);
    *(uint2*)hrh = *(const uint2*)(ghr + h4);
    *(uint2*)hzh = *(const uint2*)(ghr + HID + h4);
    *(uint2*)hnh = *(const uint2*)(ghr + 2 * HID + h4);
    float4 h = *(const float4*)(ht + (size_t)n * HID + h4);

    float2 ir0 = __half22float2(irh[0]), ir1 = __half22float2(irh[1]);
    float2 iz0 = __half22float2(izh[0]), iz1 = __half22float2(izh[1]);
    float2 in0 = __half22float2(inh[0]), in1 = __half22float2(inh[1]);
    float2 hr0 = __half22float2(hrh[0]), hr1 = __half22float2(hrh[1]);
    float2 hz0 = __half22float2(hzh[0]), hz1 = __half22float2(hzh[1]);
    float2 hn0 = __half22float2(hnh[0]), hn1 = __half22float2(hnh[1]);

    float4 o;
    o.x = gru1(ir0.x, iz0.x, in0.x, hr0.x, hz0.x, hn0.x, h.x);
    o.y = gru1(ir0.y, iz0.y, in0.y, hr0.y, hz0.y, hn0.y, h.y);
    o.z = gru1(ir1.x, iz1.x, in1.x, hr1.x, hz1.x, hn1.x, h.z);
    o.w = gru1(ir1.y, iz1.y, in1.y, hr1.y, hz1.y, hn1.y, h.w);
    *(float4*)(out + (size_t)n * HID + h4) = o;
}

// ---------------- host ----------------
extern "C" void kernel_launch(void* const* d_in, const int* in_sizes, int n_in,
                              void* d_out, int out_size)
{
    const float* traj  = (const float*)d_in[0];
    const float* neigh = (const float*)d_in[1];
    const float* dist  = (const float*)d_in[2];
    const float* ht    = (const float*)d_in[3];
    const float* W_emb = (const float*)d_in[4];
    const float* b_emb = (const float*)d_in[5];
    const float* w_ih  = (const float*)d_in[6];
    const float* w_hh  = (const float*)d_in[7];
    const float* b_ih  = (const float*)d_in[8];
    const float* b_hh  = (const float*)d_in[9];
    const int*   starts= (const int*)  d_in[10];
    float* out = (float*)d_out;

    __half *gi_p, *gh_p, *emb_p, *te_p, *wt_p, *wih_p, *whh_p, *nt_p, *ds_p, *tj_p, *htt_p;
    float* z_p;
    cudaGetSymbolAddress((void**)&gi_p,  g_gi);
    cudaGetSymbolAddress((void**)&gh_p,  g_gh);
    cudaGetSymbolAddress((void**)&emb_p, g_emb);
    cudaGetSymbolAddress((void**)&te_p,  g_temb);
    cudaGetSymbolAddress((void**)&wt_p,  g_wt);
    cudaGetSymbolAddress((void**)&wih_p, g_wih);
    cudaGetSymbolAddress((void**)&whh_p, g_whh);
    cudaGetSymbolAddress((void**)&nt_p,  g_nt);
    cudaGetSymbolAddress((void**)&ds_p,  g_ds);
    cudaGetSymbolAddress((void**)&tj_p,  g_tj);
    cudaGetSymbolAddress((void**)&htt_p, g_htt);
    cudaGetSymbolAddress((void**)&z_p,   g_zeros);

    cudaFuncSetAttribute(gemm_tc<0, true>,
                         cudaFuncAttributeMaxDynamicSharedMemorySize, SMEM_BYTES);
    cudaFuncSetAttribute(gemm_tc<1, false>,
                         cudaFuncAttributeMaxDynamicSharedMemorySize, SMEM_BYTES);

    CvtSegs segs;
    const float* srcs[6] = {neigh, dist, traj, ht, w_ih, w_hh};
    __half* dsts[6]      = {nt_p, ds_p, tj_p, htt_p, wih_p, whh_p};
    int sizes8[6] = {
        NROWS * INSZ / 8, NROWS * DDIM / 8, BSAMP * HID / 8,
        NROWS * HID / 8, G3 * HID / 8, G3 * HID / 8
    };
    int acc8 = 0;
    for (int i = 0; i < 6; i++) {
        segs.src[i] = srcs[i];
        segs.dst[i] = dsts[i];
        acc8 += sizes8[i];
        segs.end8[i] = acc8;
    }
    cvt_all_k<<<(acc8 + 255) / 256, 256>>>(segs);
    transpose_cvt_k<<<dim3(EMBK / 32, HID / 32), dim3(32, 8)>>>(W_emb, wt_p);

    // T = traj @ W2 (wt cols [64, 576)), 4096x512, no bias/relu, half out
    gemm_tc<1, false><<<dim3(BSAMP / BM, HID / BN), NTHR, SMEM_BYTES>>>(
        tj_p, nullptr, nullptr, nullptr, wt_p + INSZ, z_p, te_p, HID, EMBK, HID,
        nullptr, nullptr, nullptr, nullptr, nullptr);

    // emb = relu([neigh|dist] @ W13 + T[sid] + b_emb), K=320, half out
    gemm_tc<0, true><<<dim3(NROWS / BM, HID / BN), NTHR, SMEM_BYTES>>>(
        nullptr, nt_p, ds_p, starts, wt_p, b_emb, emb_p, KEMB, EMBK, HID,
        te_p, nullptr, nullptr, nullptr, nullptr);

    // merged dual: gi = emb @ w_ih^T + b_ih  |  gh = ht @ w_hh^T + b_hh
    gemm_tc<1, false><<<dim3(NROWS / BM, 2 * GRID_Y1), NTHR, SMEM_BYTES>>>(
        emb_p, nullptr, nullptr, nullptr, wih_p, b_ih, gi_p, HID, HID, G3,
        nullptr, htt_p, whh_p, b_hh, gh_p);

    gates_k<<<(NROWS * HID / 4) / 256, 256>>>(gi_p, gh_p, ht, out);
}

// round 16
// speedup vs baseline: 1.5661x; 1.0397x over previous
#include <cuda_runtime.h>
#include <cuda_fp16.h>
#include <cstdint>

// ---------------- problem constants ----------------
namespace {
constexpr int NROWS = 65536;
constexpr int BSAMP = 4096;
constexpr int INSZ  = 64;
constexpr int HID   = 512;
constexpr int DDIM  = 256;
constexpr int EMBK  = INSZ + HID + DDIM;  // 832
constexpr int KEMB  = INSZ + DDIM;        // 320 (emb GEMM after traj split)
constexpr int G3    = 3 * HID;            // 1536
constexpr int SRZ   = 2 * HID;            // 1024 (r|z sum matrix width)

constexpr int BM = 128, BN = 128, BK = 32, NTHR = 256;
constexpr int LDSH = 40;                         // padded smem row stride (halves) = 80B
constexpr int TILE_BYTES  = BM * LDSH * 2;       // 10240 per operand tile
constexpr int STAGE_BYTES = 2 * TILE_BYTES;      // 20480
constexpr int NSTAGE = 3;
constexpr int SMEM_BYTES = NSTAGE * STAGE_BYTES + 512;   // + sids
}

// ---------------- scratch (__device__ globals) ----------------
__device__ __half g_S   [(size_t)NROWS * SRZ];   // r|z gate pre-activation sums
__device__ __half g_in  [(size_t)NROWS * HID];   // i_n
__device__ __half g_emb [(size_t)NROWS * HID];
__device__ __half g_temb[(size_t)BSAMP * HID];   // T = traj @ W2
__device__ __half g_wt  [(size_t)HID * EMBK];    // W_emb^T in half [n][k]
__device__ __half g_wih [(size_t)G3 * HID];
__device__ __half g_whh [(size_t)G3 * HID];
__device__ __half g_nt  [(size_t)NROWS * INSZ];
__device__ __half g_ds  [(size_t)NROWS * DDIM];
__device__ __half g_tj  [(size_t)BSAMP * HID];
__device__ __half g_htt [(size_t)NROWS * HID];
__device__ float  g_zeros[HID];                  // zero bias (static zero-init)

// ---------------- helpers ----------------
__device__ __forceinline__ uint32_t smem_u32(const void* p) {
    uint32_t a;
    asm("{ .reg .u64 t; cvta.to.shared.u64 t, %1; cvt.u32.u64 %0, t; }" : "=r"(a) : "l"(p));
    return a;
}
#define CP_ASYNC16(dst, src) \
    asm volatile("cp.async.cg.shared.global [%0], [%1], 16;\n" :: "r"(dst), "l"(src))

__device__ __forceinline__ void mma_f16(float* c, const uint32_t* a, const uint32_t* b) {
    asm volatile(
        "mma.sync.aligned.m16n8k16.row.col.f32.f16.f16.f32 "
        "{%0,%1,%2,%3}, {%4,%5,%6,%7}, {%8,%9}, {%0,%1,%2,%3};"
        : "+f"(c[0]), "+f"(c[1]), "+f"(c[2]), "+f"(c[3])
        : "r"(a[0]), "r"(a[1]), "r"(a[2]), "r"(a[3]), "r"(b[0]), "r"(b[1]));
}
#define LDSM_X4(r, addr) \
    asm volatile("ldmatrix.sync.aligned.m8n8.x4.shared.b16 {%0,%1,%2,%3}, [%4];" \
                 : "=r"((r)[0]), "=r"((r)[1]), "=r"((r)[2]), "=r"((r)[3]) : "r"(addr))
#define LDSM_X2(r, addr) \
    asm volatile("ldmatrix.sync.aligned.m8n8.x2.shared.b16 {%0,%1}, [%2];" \
                 : "=r"((r)[0]), "=r"((r)[1]) : "r"(addr))

__device__ __forceinline__ float sigf(float x) { return 1.f / (1.f + expf(-x)); }

// ---------------- merged fp32 -> fp16 conversion ----------------
struct CvtSegs {
    const float* src[6];
    __half*      dst[6];
    int          end8[6];
};

__global__ void __launch_bounds__(256) cvt_all_k(CvtSegs segs) {
    int i = blockIdx.x * 256 + threadIdx.x;
    if (i >= segs.end8[5]) return;
    int s = 0;
    #pragma unroll
    for (int j = 0; j < 5; j++) s += (i >= segs.end8[j]);
    int base = (s == 0) ? 0 : segs.end8[s - 1];
    int li = i - base;
    const float4* in = (const float4*)segs.src[s];
    float4 v0 = in[li * 2];
    float4 v1 = in[li * 2 + 1];
    __half2 h[4];
    h[0] = __floats2half2_rn(v0.x, v0.y);
    h[1] = __floats2half2_rn(v0.z, v0.w);
    h[2] = __floats2half2_rn(v1.x, v1.y);
    h[3] = __floats2half2_rn(v1.z, v1.w);
    ((uint4*)segs.dst[s])[li] = *(uint4*)h;
}

__global__ void transpose_cvt_k(const float* __restrict__ W, __half* __restrict__ Wt) {
    __shared__ float t[32][33];
    int bx = blockIdx.x * 32;   // k
    int by = blockIdx.y * 32;   // n
    int tx = threadIdx.x, ty = threadIdx.y;
    #pragma unroll
    for (int i = 0; i < 4; i++)
        t[ty + i * 8][tx] = W[(size_t)(bx + ty + i * 8) * HID + (by + tx)];
    __syncthreads();
    #pragma unroll
    for (int i = 0; i < 4; i++)
        Wt[(size_t)(by + ty + i * 8) * EMBK + (bx + tx)] = __float2half(t[tx][ty + i * 8]);
}

// ---------------- fp16 mma.sync GEMM (R7 mainloop, mode-specialized) --------
// MODE 0: emb GEMM — A = [neigh|dist] (K=320), B col remap skips traj cols,
//         epilogue adds gathered Temb[sid[row]] before bias+ReLU, C half.
// MODE 1: plain GEMM — A row-major [M,K], C half.
// MODE 2: S GEMM — K=1024; A = emb (k<512) | htt (k>=512); B row j:
//         w_ih[j][k] (k<512) | w_hh[j][k-512]; bias = biasf[j]+bias2f[j]; C half.
// MODE 4: h_n GEMM + fused GRU gates — A=htt, B=w_hh n-rows; epilogue reads
//         i_n, S_r, S_z, ht and writes fp32 `out` directly.
template<int MODE, bool RELU>
__global__ void __launch_bounds__(NTHR, 2)
gemm_tc(const __half* __restrict__ A,
        const __half* __restrict__ neigh,
        const __half* __restrict__ dist,
        const int*   __restrict__ starts,
        const __half* __restrict__ B,
        const float* __restrict__ biasf,
        __half* __restrict__ C,
        int K, int ldb, int ldc,
        const __half* __restrict__ Temb,
        const __half* __restrict__ A2,
        const __half* __restrict__ B2,
        const float* __restrict__ bias2f,
        const __half* __restrict__ Sp,
        const __half* __restrict__ inp,
        const float* __restrict__ htp,
        float* __restrict__ outp)
{
    extern __shared__ __align__(16) char smem[];
    int* sids = (int*)(smem + NSTAGE * STAGE_BYTES);

    const int tid  = threadIdx.x;
    const int lane = tid & 31;
    const int warp = tid >> 5;
    const int wm = warp >> 2;
    const int wn = warp & 3;
    const int m0 = blockIdx.x * BM;
    const int n0 = blockIdx.y * BN;

    if (MODE == 0 && tid < BM) {
        int row = m0 + tid;
        int lo = 0, hi = BSAMP;
        while (lo < hi) {
            int mid = (lo + hi) >> 1;
            if (starts[mid] <= row) lo = mid + 1; else hi = mid;
        }
        sids[tid] = lo - 1;
    }
    if (MODE == 0) __syncthreads();

    const uint32_t sbase = smem_u32(smem);

    auto load_stage = [&](int s) {
        const uint32_t st = sbase + (uint32_t)((s % NSTAGE) * STAGE_BYTES);
        const int k0 = s * BK;
        #pragma unroll
        for (int i = 0; i < 2; i++) {
            int q = tid + i * NTHR;
            int row = q >> 2, c8 = (q & 3) * 8;
            uint32_t dst = st + (uint32_t)(row * LDSH + c8) * 2u;
            const __half* src;
            int gm = m0 + row;
            int kh = k0 + c8;
            if (MODE == 0) {
                src = (kh < INSZ) ? neigh + (size_t)gm * INSZ + kh
                                  : dist + (size_t)gm * DDIM + (kh - INSZ);
            } else if (MODE == 2) {
                src = (kh < HID) ? A  + (size_t)gm * HID + kh
                                 : A2 + (size_t)gm * HID + (kh - HID);
            } else {
                src = A + (size_t)gm * K + kh;
            }
            CP_ASYNC16(dst, src);
        }
        const uint32_t bb = st + (uint32_t)TILE_BYTES;
        #pragma unroll
        for (int i = 0; i < 2; i++) {
            int q = tid + i * NTHR;
            int row = q >> 2, c8 = (q & 3) * 8;
            uint32_t dst = bb + (uint32_t)(row * LDSH + c8) * 2u;
            int kh = k0 + c8;
            const __half* src;
            if (MODE == 0) {
                int kb = (kh >= INSZ) ? kh + HID : kh;         // skip traj cols
                src = B + (size_t)(n0 + row) * ldb + kb;
            } else if (MODE == 2) {
                src = (kh < HID) ? B  + (size_t)(n0 + row) * HID + kh
                                 : B2 + (size_t)(n0 + row) * HID + (kh - HID);
            } else {
                src = B + (size_t)(n0 + row) * ldb + kh;
            }
            CP_ASYNC16(dst, src);
        }
    };

    float acc[4][4][4];
    #pragma unroll
    for (int mt = 0; mt < 4; mt++)
        #pragma unroll
        for (int nt = 0; nt < 4; nt++)
            #pragma unroll
            for (int j = 0; j < 4; j++) acc[mt][nt][j] = 0.f;

    const uint32_t a_lane = (uint32_t)((wm * 64 + (lane & 15)) * LDSH + (lane >> 4) * 8) * 2u;
    const uint32_t b_lane = (uint32_t)(TILE_BYTES) +
        (uint32_t)((wn * 32 + (lane & 7)) * LDSH + ((lane >> 3) & 1) * 8) * 2u;

    const int NS = K / BK;
    load_stage(0);
    asm volatile("cp.async.commit_group;\n" ::: "memory");
    load_stage(1);
    asm volatile("cp.async.commit_group;\n" ::: "memory");

    for (int s = 0; s < NS; ++s) {
        if (s + 2 < NS) load_stage(s + 2);
        asm volatile("cp.async.commit_group;\n" ::: "memory");
        asm volatile("cp.async.wait_group 2;\n" ::: "memory");
        __syncthreads();

        const uint32_t st = sbase + (uint32_t)((s % NSTAGE) * STAGE_BYTES);
        #pragma unroll
        for (int kk = 0; kk < 2; kk++) {
            uint32_t a[4][4], b[4][2];
            #pragma unroll
            for (int mt = 0; mt < 4; mt++)
                LDSM_X4(a[mt], st + a_lane + (uint32_t)(mt * 16 * LDSH * 2 + kk * 32));
            #pragma unroll
            for (int nt = 0; nt < 4; nt++)
                LDSM_X2(b[nt], st + b_lane + (uint32_t)(nt * 8 * LDSH * 2 + kk * 32));
            #pragma unroll
            for (int mt = 0; mt < 4; mt++)
                #pragma unroll
                for (int nt = 0; nt < 4; nt++)
                    mma_f16(acc[mt][nt], a[mt], b[nt]);
        }
        __syncthreads();
    }

    // ---------------- epilogue ----------------
    #pragma unroll
    for (int mt = 0; mt < 4; mt++) {
        #pragma unroll
        for (int nt = 0; nt < 4; nt++) {
            int col = n0 + wn * 32 + nt * 8 + 2 * (lane & 3);
            int lr0 = wm * 64 + mt * 16 + (lane >> 2);
            int r0 = m0 + lr0;
            float2 bv = *(const float2*)(biasf + col);
            if (MODE == 2) {
                float2 b2 = *(const float2*)(bias2f + col);
                bv.x += b2.x; bv.y += b2.y;
            }
            float v0 = acc[mt][nt][0] + bv.x;
            float v1 = acc[mt][nt][1] + bv.y;
            float v2 = acc[mt][nt][2] + bv.x;
            float v3 = acc[mt][nt][3] + bv.y;
            if (MODE == 4) {
                // v* = h_n (fp32). Fused GRU gates -> out (fp32).
                #pragma unroll
                for (int half_ = 0; half_ < 2; half_++) {
                    int rr = r0 + half_ * 8;
                    float hn0 = half_ ? v2 : v0;
                    float hn1 = half_ ? v3 : v1;
                    float2 inn = __half22float2(*(const __half2*)(inp + (size_t)rr * HID + col));
                    float2 sr  = __half22float2(*(const __half2*)(Sp + (size_t)rr * SRZ + col));
                    float2 sz  = __half22float2(*(const __half2*)(Sp + (size_t)rr * SRZ + HID + col));
                    float2 h   = *(const float2*)(htp + (size_t)rr * HID + col);
                    float r_0 = sigf(sr.x), r_1 = sigf(sr.y);
                    float z_0 = sigf(sz.x), z_1 = sigf(sz.y);
                    float n_0 = tanhf(fmaf(r_0, hn0, inn.x));
                    float n_1 = tanhf(fmaf(r_1, hn1, inn.y));
                    float2 o = make_float2(fmaf(z_0, h.x - n_0, n_0),
                                           fmaf(z_1, h.y - n_1, n_1));
                    *(float2*)(outp + (size_t)rr * HID + col) = o;
                }
            } else {
                if (MODE == 0) {
                    float2 tA = __half22float2(
                        *(const __half2*)(Temb + (size_t)sids[lr0] * HID + col));
                    float2 tB = __half22float2(
                        *(const __half2*)(Temb + (size_t)sids[lr0 + 8] * HID + col));
                    v0 += tA.x; v1 += tA.y; v2 += tB.x; v3 += tB.y;
                }
                if (RELU) {
                    v0 = fmaxf(v0, 0.f); v1 = fmaxf(v1, 0.f);
                    v2 = fmaxf(v2, 0.f); v3 = fmaxf(v3, 0.f);
                }
                *(__half2*)(C + (size_t)r0 * ldc + col)       = __floats2half2_rn(v0, v1);
                *(__half2*)(C + (size_t)(r0 + 8) * ldc + col) = __floats2half2_rn(v2, v3);
            }
        }
    }
}

// ---------------- host ----------------
extern "C" void kernel_launch(void* const* d_in, const int* in_sizes, int n_in,
                              void* d_out, int out_size)
{
    const float* traj  = (const float*)d_in[0];
    const float* neigh = (const float*)d_in[1];
    const float* dist  = (const float*)d_in[2];
    const float* ht    = (const float*)d_in[3];
    const float* W_emb = (const float*)d_in[4];
    const float* b_emb = (const float*)d_in[5];
    const float* w_ih  = (const float*)d_in[6];
    const float* w_hh  = (const float*)d_in[7];
    const float* b_ih  = (const float*)d_in[8];
    const float* b_hh  = (const float*)d_in[9];
    const int*   starts= (const int*)  d_in[10];
    float* out = (float*)d_out;

    __half *S_p, *in_p, *emb_p, *te_p, *wt_p, *wih_p, *whh_p, *nt_p, *ds_p, *tj_p, *htt_p;
    float* z_p;
    cudaGetSymbolAddress((void**)&S_p,   g_S);
    cudaGetSymbolAddress((void**)&in_p,  g_in);
    cudaGetSymbolAddress((void**)&emb_p, g_emb);
    cudaGetSymbolAddress((void**)&te_p,  g_temb);
    cudaGetSymbolAddress((void**)&wt_p,  g_wt);
    cudaGetSymbolAddress((void**)&wih_p, g_wih);
    cudaGetSymbolAddress((void**)&whh_p, g_whh);
    cudaGetSymbolAddress((void**)&nt_p,  g_nt);
    cudaGetSymbolAddress((void**)&ds_p,  g_ds);
    cudaGetSymbolAddress((void**)&tj_p,  g_tj);
    cudaGetSymbolAddress((void**)&htt_p, g_htt);
    cudaGetSymbolAddress((void**)&z_p,   g_zeros);

    cudaFuncSetAttribute(gemm_tc<0, true>,
                         cudaFuncAttributeMaxDynamicSharedMemorySize, SMEM_BYTES);
    cudaFuncSetAttribute(gemm_tc<1, false>,
                         cudaFuncAttributeMaxDynamicSharedMemorySize, SMEM_BYTES);
    cudaFuncSetAttribute(gemm_tc<2, false>,
                         cudaFuncAttributeMaxDynamicSharedMemorySize, SMEM_BYTES);
    cudaFuncSetAttribute(gemm_tc<4, false>,
                         cudaFuncAttributeMaxDynamicSharedMemorySize, SMEM_BYTES);

    CvtSegs segs;
    const float* srcs[6] = {neigh, dist, traj, ht, w_ih, w_hh};
    __half* dsts[6]      = {nt_p, ds_p, tj_p, htt_p, wih_p, whh_p};
    int sizes8[6] = {
        NROWS * INSZ / 8, NROWS * DDIM / 8, BSAMP * HID / 8,
        NROWS * HID / 8, G3 * HID / 8, G3 * HID / 8
    };
    int acc8 = 0;
    for (int i = 0; i < 6; i++) {
        segs.src[i] = srcs[i];
        segs.dst[i] = dsts[i];
        acc8 += sizes8[i];
        segs.end8[i] = acc8;
    }
    cvt_all_k<<<(acc8 + 255) / 256, 256>>>(segs);
    transpose_cvt_k<<<dim3(EMBK / 32, HID / 32), dim3(32, 8)>>>(W_emb, wt_p);

    // T = traj @ W2 (wt cols [64,576)), 4096x512
    gemm_tc<1, false><<<dim3(BSAMP / BM, HID / BN), NTHR, SMEM_BYTES>>>(
        tj_p, nullptr, nullptr, nullptr, wt_p + INSZ, z_p, te_p, HID, EMBK, HID,
        nullptr, nullptr, nullptr, nullptr, nullptr, nullptr, nullptr, nullptr);

    // emb = relu([neigh|dist] @ W13 + T[sid] + b_emb), K=320
    gemm_tc<0, true><<<dim3(NROWS / BM, HID / BN), NTHR, SMEM_BYTES>>>(
        nullptr, nt_p, ds_p, starts, wt_p, b_emb, emb_p, KEMB, EMBK, HID,
        te_p, nullptr, nullptr, nullptr, nullptr, nullptr, nullptr, nullptr);

    // S = [emb|ht] @ [w_ih_rz|w_hh_rz]^T + (b_ih+b_hh), K=1024, N=1024
    gemm_tc<2, false><<<dim3(NROWS / BM, SRZ / BN), NTHR, SMEM_BYTES>>>(
        emb_p, nullptr, nullptr, nullptr, wih_p, b_ih, S_p, SRZ, HID, SRZ,
        nullptr, htt_p, whh_p, b_hh, nullptr, nullptr, nullptr, nullptr);

    // i_n = emb @ w_ih_n^T + b_ih_n, K=512, N=512
    gemm_tc<1, false><<<dim3(NROWS / BM, HID / BN), NTHR, SMEM_BYTES>>>(
        emb_p, nullptr, nullptr, nullptr, wih_p + (size_t)SRZ * HID, b_ih + SRZ,
        in_p, HID, HID, HID,
        nullptr, nullptr, nullptr, nullptr, nullptr, nullptr, nullptr, nullptr);

    // h_n = ht @ w_hh_n^T + b_hh_n, fused GRU gates -> out (fp32)
    gemm_tc<4, false><<<dim3(NROWS / BM, HID / BN), NTHR, SMEM_BYTES>>>(
        htt_p, nullptr, nullptr, nullptr, whh_p + (size_t)SRZ * HID, b_hh + SRZ,
        nullptr, HID, HID, HID,
        nullptr, nullptr, nullptr, nullptr, S_p, in_p, ht, out);
}